// round 12
// baseline (speedup 1.0000x reference)
#include <cuda_runtime.h>
#include <cuda_fp16.h>
#include <cstdint>

// Problem shape
#define B_DIM 4096
#define T_DIM 256
#define TD 16384             // T*D stride per batch row
#define NBI 262144           // B*64 flattened (b,i)
#define KS 68                // zchain smem row stride (floats; 272B, 16B-aligned)

// Split B fragments, plane-pair-major:
//  g_zfA[q*NBI + bi] = uint2(h01, l01)  -> planes {2q, 2q+1}
//  g_zfB[q*NBI + bi] = uint2(h89, l89)  -> planes {2q+8, 2q+9}
__device__ uint2 g_zfA[4 * NBI];
__device__ uint2 g_zfB[4 * NBI];
// A fragments (t^k hi/lo): [mf*32 + lane]
__device__ uint4 g_tfH[16 * 32];
__device__ uint4 g_tfL[16 * 32];

__constant__ float c_coef[13] = {
    1.0f, 1.0f, 0.5f, 1.6666666666667e-1f, 4.1666666666667e-2f,
    8.3333333333333e-3f, 1.3888888888889e-3f, 1.9841269841270e-4f,
    2.4801587301587e-5f, 2.7557319223986e-6f, 2.7557319223986e-7f,
    2.5052108385442e-8f, 2.0876756987868e-9f};

// ---------------- helpers ----------------
__device__ __forceinline__ void split2h(float x, float y, uint32_t& H, uint32_t& L) {
    __half hx = __float2half_rn(x);
    __half hy = __float2half_rn(y);
    __half lx = __float2half_rn(x - __half2float(hx));
    __half ly = __float2half_rn(y - __half2float(hy));
    __half2 hh = __halves2half2(hx, hy);
    __half2 ll = __halves2half2(lx, ly);
    H = *(uint32_t*)&hh;
    L = *(uint32_t*)&ll;
}
__device__ __forceinline__ void mma16816h(float* c, const uint4& a, uint32_t b0, uint32_t b1) {
    asm volatile(
        "mma.sync.aligned.m16n8k16.row.col.f32.f16.f16.f32 "
        "{%0,%1,%2,%3}, {%4,%5,%6,%7}, {%8,%9}, {%0,%1,%2,%3};"
        : "+f"(c[0]), "+f"(c[1]), "+f"(c[2]), "+f"(c[3])
        : "r"(a.x), "r"(a.y), "r"(a.z), "r"(a.w), "r"(b0), "r"(b1));
}

// ---------------- zchain: fused local power chain + Taylor planes + pack ------
// Blocks 0..511: 8 b-rows each. Thread (ty = tid>>4, tx = tid&15) owns row ty,
// cols 4tx..4tx+3. Iterates Y_k = Y_{k-1} @ K^T in smem (K^T resident),
// keeps y_k in registers, packs split-fp16 fragments at the end.
// Blocks 512..515: t^k fragment build.
extern "C" __global__ void __launch_bounds__(128)
zchain_kernel(const float* __restrict__ inputs, const float* __restrict__ Kmat,
              const float* __restrict__ time) {
    if (blockIdx.x >= 512) {
        int e = (blockIdx.x - 512) * 128 + threadIdx.x;   // 0..511 = mf*32 + lane
        int lane = e & 31;
        int mf = e >> 5;
        int r0 = mf * 16 + (lane >> 2);
        int r1 = r0 + 8;
        int k0 = (lane & 3) * 2;

        float t0 = time[r0], t1 = time[r1];
        float p0[16], p1[16];
        p0[0] = 1.f; p1[0] = 1.f;
#pragma unroll
        for (int k = 1; k < 13; k++) { p0[k] = p0[k - 1] * t0; p1[k] = p1[k - 1] * t1; }
#pragma unroll
        for (int k = 13; k < 16; k++) { p0[k] = 0.f; p1[k] = 0.f; }

        uint4 H, L;
        split2h(p0[k0], p0[k0 + 1], H.x, L.x);
        split2h(p1[k0], p1[k0 + 1], H.y, L.y);
        split2h(p0[k0 + 8], p0[k0 + 9], H.z, L.z);
        split2h(p1[k0 + 8], p1[k0 + 9], H.w, L.w);
        g_tfH[e] = H;
        g_tfL[e] = L;
        return;
    }

    __shared__ float kk[64 * KS];      // kk[j*KS + c] = K[c][j]  (K^T row-major)
    __shared__ float vb[2][8 * KS];    // ping-pong Y tiles, row stride KS

    const int tid = threadIdx.x;
    const int ty = tid >> 4;           // 0..7 local b row
    const int tx = tid & 15;           // col group: 4tx..4tx+3
    const int b0 = blockIdx.x * 8;

    // load K^T: coalesced global read, transposed smem store (one-time)
#pragma unroll
    for (int l = 0; l < 32; l++) {
        int idx = l * 128 + tid;       // idx = c*64 + j
        int c = idx >> 6, j = idx & 63;
        kk[j * KS + c] = Kmat[idx];
    }

    // load x0 rows b0..b0+7; thread's own quad doubles as y[0]
    float y[16][4];
    {
        float4 v4 = *(const float4*)(inputs + (size_t)(b0 + ty) * TD + 4 * tx);
        *(float4*)&vb[0][ty * KS + 4 * tx] = v4;
        y[0][0] = v4.x; y[0][1] = v4.y; y[0][2] = v4.z; y[0][3] = v4.w;
    }
#pragma unroll
    for (int k = 13; k < 16; k++)
#pragma unroll
        for (int c = 0; c < 4; c++) y[k][c] = 0.f;
    __syncthreads();

    int cur = 0;
#pragma unroll 1
    for (int k = 1; k <= 12; k++) {
        float s0 = 0.f, s1 = 0.f, s2 = 0.f, s3 = 0.f;
#pragma unroll
        for (int jc = 0; jc < 16; jc++) {
            float4 av = *(const float4*)&vb[cur][ty * KS + 4 * jc];
            float4 bv0 = *(const float4*)&kk[(4 * jc + 0) * KS + 4 * tx];
            float4 bv1 = *(const float4*)&kk[(4 * jc + 1) * KS + 4 * tx];
            float4 bv2 = *(const float4*)&kk[(4 * jc + 2) * KS + 4 * tx];
            float4 bv3 = *(const float4*)&kk[(4 * jc + 3) * KS + 4 * tx];
            s0 = fmaf(av.x, bv0.x, s0); s1 = fmaf(av.x, bv0.y, s1);
            s2 = fmaf(av.x, bv0.z, s2); s3 = fmaf(av.x, bv0.w, s3);
            s0 = fmaf(av.y, bv1.x, s0); s1 = fmaf(av.y, bv1.y, s1);
            s2 = fmaf(av.y, bv1.z, s2); s3 = fmaf(av.y, bv1.w, s3);
            s0 = fmaf(av.z, bv2.x, s0); s1 = fmaf(av.z, bv2.y, s1);
            s2 = fmaf(av.z, bv2.z, s2); s3 = fmaf(av.z, bv2.w, s3);
            s0 = fmaf(av.w, bv3.x, s0); s1 = fmaf(av.w, bv3.y, s1);
            s2 = fmaf(av.w, bv3.z, s2); s3 = fmaf(av.w, bv3.w, s3);
        }
        y[k][0] = s0; y[k][1] = s1; y[k][2] = s2; y[k][3] = s3;
        *(float4*)&vb[cur ^ 1][ty * KS + 4 * tx] = make_float4(s0, s1, s2, s3);
        cur ^= 1;
        __syncthreads();
    }

    // scale by Taylor coefficients
#pragma unroll
    for (int k = 1; k <= 12; k++)
#pragma unroll
        for (int c = 0; c < 4; c++) y[k][c] *= c_coef[k];

    // pack fragments: thread's 4 contiguous bi -> 2 uint4 per (q, array)
    const int bi = (b0 + ty) * 64 + 4 * tx;
#pragma unroll
    for (int q = 0; q < 4; q++) {
        uint2 ea[4], eb[4];
#pragma unroll
        for (int c = 0; c < 4; c++) {
            split2h(y[2 * q][c],     y[2 * q + 1][c], ea[c].x, ea[c].y);
            split2h(y[2 * q + 8][c], y[2 * q + 9][c], eb[c].x, eb[c].y);
        }
        uint2* dA = g_zfA + (size_t)q * NBI + bi;
        uint2* dB = g_zfB + (size_t)q * NBI + bi;
        *(uint4*)&dA[0] = make_uint4(ea[0].x, ea[0].y, ea[1].x, ea[1].y);
        *(uint4*)&dA[2] = make_uint4(ea[2].x, ea[2].y, ea[3].x, ea[3].y);
        *(uint4*)&dB[0] = make_uint4(eb[0].x, eb[0].y, eb[1].x, eb[1].y);
        *(uint4*)&dB[2] = make_uint4(eb[2].x, eb[2].y, eb[3].x, eb[3].y);
    }
}

// ---------------- eval: R9/R11 staged version (measured ~48us, unchanged) ------
// grid (512, 2) x 256 thr. Warp W = blockIdx.x*8+wid owns b-row W (64 bi);
// blockIdx.y selects 8 of 16 t-fragment rows. 3-term fp16 split.
#define STRIDE 72
extern "C" __global__ void __launch_bounds__(256)
eval_kernel(float* __restrict__ out) {
    __shared__ float stg[8 * 16 * STRIDE];
    const int tid = threadIdx.x;
    const int wid = tid >> 5, lane = tid & 31;
    const int W = blockIdx.x * 8 + wid;          // b index
    const int mf0 = blockIdx.y * 8;
    float* ws = stg + wid * 16 * STRIDE;

    const int q = lane & 3;
    const int nl = lane >> 2;
    const size_t zbase = (size_t)q * NBI + W * 64 + nl;
    uint2 zA[8], zB[8];
#pragma unroll
    for (int nf = 0; nf < 8; nf++) {
        zA[nf] = g_zfA[zbase + nf * 8];
        zB[nf] = g_zfB[zbase + nf * 8];
    }

    const int r = lane >> 2;
    const int cb = (lane & 3) * 2;
    float* obase = out + (size_t)W * TD;

#pragma unroll 1
    for (int mi = 0; mi < 8; mi++) {
        const int mf = mf0 + mi;
        uint4 ah = g_tfH[mf * 32 + lane];
        uint4 al = g_tfL[mf * 32 + lane];

        float acc[8][4];
#pragma unroll
        for (int nf = 0; nf < 8; nf++)
#pragma unroll
            for (int q2 = 0; q2 < 4; q2++) acc[nf][q2] = 0.f;

#pragma unroll
        for (int nf = 0; nf < 8; nf++) {
            mma16816h(acc[nf], ah, zA[nf].x, zB[nf].x);   // hi * hi
            mma16816h(acc[nf], ah, zA[nf].y, zB[nf].y);   // hi * lo
            mma16816h(acc[nf], al, zA[nf].x, zB[nf].x);   // lo * hi
        }

        // stage tile [16 t][64 i]
#pragma unroll
        for (int nf = 0; nf < 8; nf++) {
            int col = nf * 8 + cb;
            *(float2*)&ws[r * STRIDE + col]       = make_float2(acc[nf][0], acc[nf][1]);
            *(float2*)&ws[(r + 8) * STRIDE + col] = make_float2(acc[nf][2], acc[nf][3]);
        }
        __syncwarp();

        // contiguous stores: out[b][mf*16 .. +15][0..63] = 4KB contiguous
        float* op = obase + (size_t)mf * 1024;
#pragma unroll
        for (int p = 0; p < 8; p++) {
            int row = p * 2 + (lane >> 4);
            int col = (lane & 15) * 4;
            float4 vq = *(float4*)&ws[row * STRIDE + col];
            *(float4*)(op + row * 64 + col) = vq;
        }
        __syncwarp();
    }
}

// ---------------- launch ----------------
extern "C" void kernel_launch(void* const* d_in, const int* in_sizes, int n_in,
                              void* d_out, int out_size) {
    const float* inputs = (const float*)d_in[0];
    const float* time   = (const float*)d_in[1];
    const float* kern   = (const float*)d_in[2];
    float* out = (float*)d_out;

    zchain_kernel<<<516, 128>>>(inputs, kern, time);
    eval_kernel<<<dim3(512, 2), 256>>>(out);
}

// round 13
// speedup vs baseline: 1.2804x; 1.2804x over previous
#include <cuda_runtime.h>
#include <cuda_fp16.h>
#include <cstdint>

// Problem shape
#define B_DIM 4096
#define T_DIM 256
#define TD 16384             // T*D stride per batch row
#define NBI 262144           // B*64 flattened (b,i)
#define JCS 65               // zgp chunk stride in float4 (bank spread)

// K powers: g_Kp[(k-1)*4096 + i*64 + j] = (K^k)[i][j], k=1..12
__device__ float g_Kp[12 * 4096];
// Split B fragments, plane-pair-major:
//  g_zfA[q*NBI + bi] = uint2(h01, l01)  -> planes {2q, 2q+1}
//  g_zfB[q*NBI + bi] = uint2(h89, l89)  -> planes {2q+8, 2q+9}
__device__ uint2 g_zfA[4 * NBI];
__device__ uint2 g_zfB[4 * NBI];
// A fragments (t^k hi/lo): [mf*32 + lane]
__device__ uint4 g_tfH[16 * 32];
__device__ uint4 g_tfL[16 * 32];

__constant__ float c_coef[13] = {
    1.0f, 1.0f, 0.5f, 1.6666666666667e-1f, 4.1666666666667e-2f,
    8.3333333333333e-3f, 1.3888888888889e-3f, 1.9841269841270e-4f,
    2.4801587301587e-5f, 2.7557319223986e-6f, 2.7557319223986e-7f,
    2.5052108385442e-8f, 2.0876756987868e-9f};

// ---------------- helpers ----------------
__device__ __forceinline__ void split2h(float x, float y, uint32_t& H, uint32_t& L) {
    __half hx = __float2half_rn(x);
    __half hy = __float2half_rn(y);
    __half lx = __float2half_rn(x - __half2float(hx));
    __half ly = __float2half_rn(y - __half2float(hy));
    __half2 hh = __halves2half2(hx, hy);
    __half2 ll = __halves2half2(lx, ly);
    H = *(uint32_t*)&hh;
    L = *(uint32_t*)&ll;
}
__device__ __forceinline__ void mma16816h(float* c, const uint4& a, uint32_t b0, uint32_t b1) {
    asm volatile(
        "mma.sync.aligned.m16n8k16.row.col.f32.f16.f16.f32 "
        "{%0,%1,%2,%3}, {%4,%5,%6,%7}, {%8,%9}, {%0,%1,%2,%3};"
        : "+f"(c[0]), "+f"(c[1]), "+f"(c[2]), "+f"(c[3])
        : "r"(a.x), "r"(a.y), "r"(a.z), "r"(a.w), "r"(b0), "r"(b1));
}
__device__ __forceinline__ void stg_cs4(float* p, float4 v) {
    asm volatile("st.global.cs.v4.f32 [%0], {%1, %2, %3, %4};"
                 :: "l"(p), "f"(v.x), "f"(v.y), "f"(v.z), "f"(v.w) : "memory");
}

// ---------------- kpow (+ t-fragments) — R9/R11-measured (6us) ----------------
extern "C" __global__ void __launch_bounds__(64)
kpow_kernel(const float* __restrict__ Kmat, const float* __restrict__ time) {
    if (blockIdx.x >= 64) {
        int e = (blockIdx.x - 64) * 64 + threadIdx.x;   // 0..511 = mf*32 + lane
        int lane = e & 31;
        int mf = e >> 5;
        int r0 = mf * 16 + (lane >> 2);
        int r1 = r0 + 8;
        int k0 = (lane & 3) * 2;

        float t0 = time[r0], t1 = time[r1];
        float p0[16], p1[16];
        p0[0] = 1.f; p1[0] = 1.f;
#pragma unroll
        for (int k = 1; k < 13; k++) { p0[k] = p0[k - 1] * t0; p1[k] = p1[k - 1] * t1; }
#pragma unroll
        for (int k = 13; k < 16; k++) { p0[k] = 0.f; p1[k] = 0.f; }

        uint4 H, L;
        split2h(p0[k0], p0[k0 + 1], H.x, L.x);
        split2h(p1[k0], p1[k0 + 1], H.y, L.y);
        split2h(p0[k0 + 8], p0[k0 + 9], H.z, L.z);
        split2h(p1[k0 + 8], p1[k0 + 9], H.w, L.w);
        g_tfH[e] = H;
        g_tfL[e] = L;
        return;
    }

    __shared__ float vbuf[2][64];
    const int i = threadIdx.x;
    const int c = blockIdx.x;

    float kr[64];
    {
        const float4* kp = (const float4*)(Kmat + i * 64);
#pragma unroll
        for (int q = 0; q < 16; q++) {
            float4 v = kp[q];
            kr[q * 4 + 0] = v.x; kr[q * 4 + 1] = v.y;
            kr[q * 4 + 2] = v.z; kr[q * 4 + 3] = v.w;
        }
    }

    float v0 = Kmat[i * 64 + c];
    vbuf[0][i] = v0;
    g_Kp[i * 64 + c] = v0;
    __syncthreads();

    int cur = 0;
#pragma unroll
    for (int k = 2; k <= 12; k++) {
        const float4* vq = (const float4*)vbuf[cur];
        float s0 = 0.f, s1 = 0.f, s2 = 0.f, s3 = 0.f;
#pragma unroll
        for (int jq = 0; jq < 16; jq++) {
            float4 vv = vq[jq];
            s0 = fmaf(kr[jq * 4 + 0], vv.x, s0);
            s1 = fmaf(kr[jq * 4 + 1], vv.y, s1);
            s2 = fmaf(kr[jq * 4 + 2], vv.z, s2);
            s3 = fmaf(kr[jq * 4 + 3], vv.w, s3);
        }
        float s = (s0 + s1) + (s2 + s3);
        vbuf[cur ^ 1][i] = s;
        g_Kp[(k - 1) * 4096 + i * 64 + c] = s;
        cur ^= 1;
        __syncthreads();
    }
}

// ---------------- zgp: plane-pair GEMM, conflict-free chunked tiles (R11) ------
extern "C" __global__ void __launch_bounds__(256)
zgp_kernel(const float* __restrict__ inputs) {
    __shared__ float4 xs[16 * JCS];
    __shared__ float4 ks[16 * JCS];
    const int tid = threadIdx.x;
    const int ty = tid >> 4, tx = tid & 15;
    const int b0 = blockIdx.x * 64;
    const int p = blockIdx.y;
    uint2* dst = (p < 4 ? g_zfA : g_zfB) + (size_t)(p & 3) * NBI;

    if (p == 7) {
        // planes 14,15: identically zero (contiguous uint4 fill)
#pragma unroll
        for (int r = 0; r < 4; r++) {
            int bi = (b0 + ty * 4 + r) * 64 + tx * 4;
            *(uint4*)&dst[bi]     = make_uint4(0, 0, 0, 0);
            *(uint4*)&dst[bi + 2] = make_uint4(0, 0, 0, 0);
        }
        return;
    }

    // load x0 tile: xs[(j>>2)*JCS + r] = x0[b0+r][j..j+3]
#pragma unroll
    for (int l = 0; l < 4; l++) {
        int idx4 = l * 256 + tid;
        int el = idx4 * 4;
        int r = el >> 6, j = el & 63;
        xs[(j >> 2) * JCS + r] = *(const float4*)(inputs + (size_t)(b0 + r) * TD + j);
    }
    __syncthreads();

    float accP[2][4][4];
#pragma unroll
    for (int pl = 0; pl < 2; pl++)
#pragma unroll
        for (int r = 0; r < 4; r++)
#pragma unroll
            for (int c = 0; c < 4; c++) accP[pl][r][c] = 0.f;

#pragma unroll
    for (int pl = 0; pl < 2; pl++) {
        const int kk = 2 * p + pl;
        if (kk == 0) {
#pragma unroll
            for (int r = 0; r < 4; r++)
#pragma unroll
                for (int c = 0; c < 4; c++) {
                    int j = tx + 16 * c;
                    accP[0][r][c] = ((const float*)&xs[(j >> 2) * JCS + ty * 4 + r])[j & 3];
                }
        } else if (kk <= 12) {
            const float* kp = g_Kp + (kk - 1) * 4096;
#pragma unroll
            for (int l = 0; l < 4; l++) {
                int idx4 = l * 256 + tid;
                int el = idx4 * 4;
                int r = el >> 6, j = el & 63;
                ks[(j >> 2) * JCS + r] = *(const float4*)(kp + el);
            }
            __syncthreads();
#pragma unroll 4
            for (int jc = 0; jc < 16; jc++) {
                float4 a4[4], b4[4];
#pragma unroll
                for (int r = 0; r < 4; r++) a4[r] = xs[jc * JCS + ty * 4 + r];
#pragma unroll
                for (int c = 0; c < 4; c++) b4[c] = ks[jc * JCS + tx + 16 * c];
#pragma unroll
                for (int r = 0; r < 4; r++)
#pragma unroll
                    for (int c = 0; c < 4; c++) {
                        float s = accP[pl][r][c];
                        s = fmaf(a4[r].x, b4[c].x, s);
                        s = fmaf(a4[r].y, b4[c].y, s);
                        s = fmaf(a4[r].z, b4[c].z, s);
                        s = fmaf(a4[r].w, b4[c].w, s);
                        accP[pl][r][c] = s;
                    }
            }
            __syncthreads();   // before next plane's ks load
        }
        // kk == 13: stays zero
    }

    const float ck0 = (2 * p     <= 12) ? c_coef[2 * p]     : 0.f;
    const float ck1 = (2 * p + 1 <= 12) ? c_coef[2 * p + 1] : 0.f;

    // store: element (b0+ty*4+r, tx+16c) -> dst[bi]; per-warp 2x128B runs per STG
#pragma unroll
    for (int r = 0; r < 4; r++) {
        int bir = (b0 + ty * 4 + r) * 64 + tx;
#pragma unroll
        for (int c = 0; c < 4; c++) {
            uint32_t h, l;
            split2h(accP[0][r][c] * ck0, accP[1][r][c] * ck1, h, l);
            dst[bir + 16 * c] = make_uint2(h, l);
        }
    }
}

// ---------------- eval: R11 staged version + streaming stores ----------------
// grid (512, 2) x 256 thr. Warp W = blockIdx.x*8+wid owns b-row W (64 bi);
// blockIdx.y selects 8 of 16 t-fragment rows. 3-term fp16 split.
#define STRIDE 72
extern "C" __global__ void __launch_bounds__(256)
eval_kernel(float* __restrict__ out) {
    __shared__ float stg[8 * 16 * STRIDE];
    const int tid = threadIdx.x;
    const int wid = tid >> 5, lane = tid & 31;
    const int W = blockIdx.x * 8 + wid;          // b index
    const int mf0 = blockIdx.y * 8;
    float* ws = stg + wid * 16 * STRIDE;

    const int q = lane & 3;
    const int nl = lane >> 2;
    const size_t zbase = (size_t)q * NBI + W * 64 + nl;
    uint2 zA[8], zB[8];
#pragma unroll
    for (int nf = 0; nf < 8; nf++) {
        zA[nf] = g_zfA[zbase + nf * 8];
        zB[nf] = g_zfB[zbase + nf * 8];
    }

    const int r = lane >> 2;
    const int cb = (lane & 3) * 2;
    float* obase = out + (size_t)W * TD;

#pragma unroll 1
    for (int mi = 0; mi < 8; mi++) {
        const int mf = mf0 + mi;
        uint4 ah = g_tfH[mf * 32 + lane];
        uint4 al = g_tfL[mf * 32 + lane];

        float acc[8][4];
#pragma unroll
        for (int nf = 0; nf < 8; nf++)
#pragma unroll
            for (int q2 = 0; q2 < 4; q2++) acc[nf][q2] = 0.f;

#pragma unroll
        for (int nf = 0; nf < 8; nf++) {
            mma16816h(acc[nf], ah, zA[nf].x, zB[nf].x);   // hi * hi
            mma16816h(acc[nf], ah, zA[nf].y, zB[nf].y);   // hi * lo
            mma16816h(acc[nf], al, zA[nf].x, zB[nf].x);   // lo * hi
        }

        // stage tile [16 t][64 i]
#pragma unroll
        for (int nf = 0; nf < 8; nf++) {
            int col = nf * 8 + cb;
            *(float2*)&ws[r * STRIDE + col]       = make_float2(acc[nf][0], acc[nf][1]);
            *(float2*)&ws[(r + 8) * STRIDE + col] = make_float2(acc[nf][2], acc[nf][3]);
        }
        __syncwarp();

        // contiguous streaming stores: out[b][mf*16 .. +15][0..63] = 4KB contiguous
        float* op = obase + (size_t)mf * 1024;
#pragma unroll
        for (int p = 0; p < 8; p++) {
            int row = p * 2 + (lane >> 4);
            int col = (lane & 15) * 4;
            float4 vq = *(float4*)&ws[row * STRIDE + col];
            stg_cs4(op + row * 64 + col, vq);
        }
        __syncwarp();
    }
}

// ---------------- launch ----------------
extern "C" void kernel_launch(void* const* d_in, const int* in_sizes, int n_in,
                              void* d_out, int out_size) {
    const float* inputs = (const float*)d_in[0];
    const float* time   = (const float*)d_in[1];
    const float* kern   = (const float*)d_in[2];
    float* out = (float*)d_out;

    kpow_kernel<<<72, 64>>>(kern, time);
    zgp_kernel<<<dim3(64, 8), 256>>>(inputs);
    eval_kernel<<<dim3(512, 2), 256>>>(out);
}